// round 8
// baseline (speedup 1.0000x reference)
#include <cuda_runtime.h>
#include <math.h>

// ---------------------------------------------------------------------------
// TrendsGRU: out[t,b,:] = GRU-scan(x) @ Wo + bo
// T=512, B=64, I=512, H=1024, O=512
//
// Plan:
//   1) pre-GEMM  : g_gx[t*B+b, 0:3H] = x @ [Wz_x|Wr_x|Wh_x] + [bz|br|bh]
//   2) persistent scan kernel (128 CTAs, recurrent weights staged in SMEM,
//      software grid barrier, 2 barriers/step)
//   3) post-GEMM : out = h_all @ Wo + bo
// All fp32.
// ---------------------------------------------------------------------------

#define TT 512
#define BB 64
#define II 512
#define HH 1024
#define OO 512
#define H3 3072
#define TB (TT * BB) // 32768

// -------------------------- scratch (device globals) -----------------------
__device__ float g_gx[(size_t)TB * H3];           // 402 MB: gate pre-activations (x part + bias)
__device__ float g_h[(size_t)(TT + 1) * BB * HH]; // 134 MB: h_all, slot 0 = zeros
__device__ float g_z[BB * HH];                    // z gate (current step)
__device__ float g_hr[BB * HH];                   // h*r     (current step)
__device__ unsigned g_barCount;                   // zero-init
__device__ unsigned g_barGen;                     // zero-init (monotone across launches: fine)

// ---------------------------------------------------------------------------
// Generic fp32 SGEMM with bias: C[M,N] = A[M,K] @ Bw[K,N] + bias[N]
// BM=128, BN=64, BK=16, 256 threads, 8x4 register tile, reg-prefetch of tiles.
// All dims must divide the tile sizes (they do here).
// ---------------------------------------------------------------------------
#define GM 128
#define GN 64
#define GK 16
#define GT 256
#define AP 132 // padded pitch for As[k][m]
#define BP 68  // padded pitch for Bs[k][n]

__global__ __launch_bounds__(GT) void sgemm_bias(
    const float* __restrict__ A, const float* __restrict__ Bw,
    const float* __restrict__ bias, float* __restrict__ C,
    int K, int lda, int ldb, int ldc)
{
    __shared__ float As[GK * AP];
    __shared__ float Bs[GK * BP];

    const int t = threadIdx.x;
    const int m0 = blockIdx.y * GM;
    const int n0 = blockIdx.x * GN;

    // A tile load mapping: 512 float4s, 2 per thread
    const int am0 = t >> 2, akq0 = t & 3;
    const int am1 = (t + GT) >> 2, akq1 = (t + GT) & 3;
    // B tile load mapping: 256 float4s, 1 per thread
    const int bkr = t >> 4, bnq = t & 15;

    const float* Aptr0 = A + (size_t)(m0 + am0) * lda + akq0 * 4;
    const float* Aptr1 = A + (size_t)(m0 + am1) * lda + akq1 * 4;
    const float* Bptr  = Bw + (size_t)bkr * ldb + n0 + bnq * 4;

    // compute mapping: rows r0..r0+7, cols c0..c0+3
    const int r0 = (t & 15) * 8;
    const int c0 = (t >> 4) * 4;

    float acc[8][4];
#pragma unroll
    for (int i = 0; i < 8; i++)
#pragma unroll
        for (int j = 0; j < 4; j++) acc[i][j] = 0.f;

    float4 apf0 = *(const float4*)(Aptr0);
    float4 apf1 = *(const float4*)(Aptr1);
    float4 bpf  = *(const float4*)(Bptr);

    const int nkt = K / GK;
    for (int kt = 0; kt < nkt; ++kt) {
        // stage prefetched tile into smem (As transposed [k][m])
        As[(akq0 * 4 + 0) * AP + am0] = apf0.x;
        As[(akq0 * 4 + 1) * AP + am0] = apf0.y;
        As[(akq0 * 4 + 2) * AP + am0] = apf0.z;
        As[(akq0 * 4 + 3) * AP + am0] = apf0.w;
        As[(akq1 * 4 + 0) * AP + am1] = apf1.x;
        As[(akq1 * 4 + 1) * AP + am1] = apf1.y;
        As[(akq1 * 4 + 2) * AP + am1] = apf1.z;
        As[(akq1 * 4 + 3) * AP + am1] = apf1.w;
        *(float4*)&Bs[bkr * BP + bnq * 4] = bpf;
        __syncthreads();

        if (kt + 1 < nkt) { // prefetch next tile while computing
            apf0 = *(const float4*)(Aptr0 + (kt + 1) * GK);
            apf1 = *(const float4*)(Aptr1 + (kt + 1) * GK);
            bpf  = *(const float4*)(Bptr + (size_t)(kt + 1) * GK * ldb);
        }

#pragma unroll 8
        for (int k = 0; k < GK; k++) {
            const float* ar = &As[k * AP + r0];
            float4 a0 = *(const float4*)(ar);
            float4 a1 = *(const float4*)(ar + 4);
            float4 b4 = *(const float4*)&Bs[k * BP + c0];
            float av[8] = {a0.x, a0.y, a0.z, a0.w, a1.x, a1.y, a1.z, a1.w};
            float bv[4] = {b4.x, b4.y, b4.z, b4.w};
#pragma unroll
            for (int i = 0; i < 8; i++)
#pragma unroll
                for (int j = 0; j < 4; j++) acc[i][j] += av[i] * bv[j];
        }
        __syncthreads();
    }

    float4 bb = *(const float4*)&bias[n0 + c0];
#pragma unroll
    for (int i = 0; i < 8; i++) {
        float4 o = make_float4(acc[i][0] + bb.x, acc[i][1] + bb.y,
                               acc[i][2] + bb.z, acc[i][3] + bb.w);
        *(float4*)&C[(size_t)(m0 + r0 + i) * ldc + n0 + c0] = o;
    }
}

// ---------------------------------------------------------------------------
// Persistent GRU scan kernel
// ---------------------------------------------------------------------------
#define NCTA 128
#define STHR 128
#define ZRC 16 // zr columns per CTA (2048/128)
#define HCC 8  // candidate columns per CTA (1024/128)
#define TK 64  // h k-tile
#define HP 68  // padded h_s pitch
#define SMEM_SCAN ((HH * ZRC + HH * HCC + TK * HP) * 4)

__device__ __forceinline__ float sigmoidf_(float v) { return 1.f / (1.f + __expf(-v)); }
__device__ __forceinline__ float4 ldcg4(const float* p) { return __ldcg((const float4*)p); }

__device__ __forceinline__ void grid_barrier()
{
    __threadfence();   // publish this thread's writes
    __syncthreads();
    if (threadIdx.x == 0) {
        volatile unsigned* genp = &g_barGen;
        unsigned gen = *genp;
        unsigned arrived = atomicAdd(&g_barCount, 1u);
        if (arrived == NCTA - 1) {
            atomicExch(&g_barCount, 0u);
            __threadfence();
            atomicAdd(&g_barGen, 1u);
        } else {
            while (*genp == gen) { __nanosleep(64); }
        }
    }
    __syncthreads();
    __threadfence();
}

__global__ __launch_bounds__(STHR) void gru_scan(
    const float* __restrict__ Wz, const float* __restrict__ Wr,
    const float* __restrict__ Wh)
{
    extern __shared__ float sm[];
    float* Wzr_s = sm;                       // [1024][ZRC]
    float* Wh_s  = sm + HH * ZRC;            // [1024][HCC]
    float* h_s   = sm + HH * ZRC + HH * HCC; // [TK][HP]

    const int tid = threadIdx.x;
    const int c = blockIdx.x;

    // ---- stage recurrent weight slices into SMEM (once) ----
    for (int idx = tid; idx < HH * ZRC; idx += STHR) {
        int k = idx / ZRC, j = idx - k * ZRC;
        int jg = c * ZRC + j; // global zr column (0..2047)
        Wzr_s[idx] = (jg < HH) ? Wz[(size_t)(II + k) * HH + jg]
                               : Wr[(size_t)(II + k) * HH + (jg - HH)];
    }
    for (int idx = tid; idx < HH * HCC; idx += STHR) {
        int k = idx / HCC, j = idx - k * HCC;
        Wh_s[idx] = Wh[(size_t)(II + k) * HH + (c * HCC + j)];
    }
    // zero h slot 0 (h0 = 0), re-done every launch for determinism
    for (int idx = c * STHR + tid; idx < BB * HH; idx += NCTA * STHR) g_h[idx] = 0.f;
    grid_barrier();

    const int p1r0 = (tid & 15) * 4; // phase1: 4 rows x 2 cols per thread
    const int p1c0 = (tid >> 4) * 2;
    const int p2r0 = (tid >> 2) * 2; // phase2: 2 rows x 2 cols per thread
    const int p2c0 = (tid & 3) * 2;

    for (int t = 0; t < TT; ++t) {
        const float* hprev = g_h + (size_t)t * BB * HH;
        const float* gx = g_gx + (size_t)t * BB * H3;

        // ================= phase 1: zr = hprev @ Wzr_slice =================
        float a00 = 0, a01 = 0, a10 = 0, a11 = 0, a20 = 0, a21 = 0, a30 = 0, a31 = 0;
        float4 pf[8];
#pragma unroll
        for (int i = 0; i < 8; i++) {
            int f = tid + STHR * i, b = f >> 4, kq = f & 15;
            pf[i] = ldcg4(hprev + (size_t)b * HH + kq * 4);
        }
        for (int kt = 0; kt < HH / TK; ++kt) {
#pragma unroll
            for (int i = 0; i < 8; i++) { // regs -> smem, transposed [k][b]
                int f = tid + STHR * i, b = f >> 4, kk = (f & 15) * 4;
                h_s[(kk + 0) * HP + b] = pf[i].x;
                h_s[(kk + 1) * HP + b] = pf[i].y;
                h_s[(kk + 2) * HP + b] = pf[i].z;
                h_s[(kk + 3) * HP + b] = pf[i].w;
            }
            __syncthreads();
            if (kt + 1 < HH / TK) {
#pragma unroll
                for (int i = 0; i < 8; i++) {
                    int f = tid + STHR * i, b = f >> 4, kq = f & 15;
                    pf[i] = ldcg4(hprev + (size_t)b * HH + (kt + 1) * TK + kq * 4);
                }
            }
            const float* wb = Wzr_s + kt * TK * ZRC;
#pragma unroll 4
            for (int kk = 0; kk < TK; ++kk) {
                float4 hv = *(const float4*)&h_s[kk * HP + p1r0];
                float2 wv = *(const float2*)&wb[kk * ZRC + p1c0];
                a00 += hv.x * wv.x; a01 += hv.x * wv.y;
                a10 += hv.y * wv.x; a11 += hv.y * wv.y;
                a20 += hv.z * wv.x; a21 += hv.z * wv.y;
                a30 += hv.w * wv.x; a31 += hv.w * wv.y;
            }
            __syncthreads();
        }
        { // epilogue: add gx, sigmoid, publish z or h*r
            float accs[4][2] = {{a00, a01}, {a10, a11}, {a20, a21}, {a30, a31}};
            int jg0 = c * ZRC + p1c0;
            if (jg0 < HH) { // z columns (CTAs 0..63)
#pragma unroll
                for (int ri = 0; ri < 4; ++ri) {
                    int b = p1r0 + ri;
#pragma unroll
                    for (int ci = 0; ci < 2; ++ci) {
                        int jg = jg0 + ci;
                        float v = accs[ri][ci] + gx[(size_t)b * H3 + jg];
                        g_z[b * HH + jg] = sigmoidf_(v);
                    }
                }
            } else { // r columns (CTAs 64..127): publish h*r directly
#pragma unroll
                for (int ri = 0; ri < 4; ++ri) {
                    int b = p1r0 + ri;
#pragma unroll
                    for (int ci = 0; ci < 2; ++ci) {
                        int jg = jg0 + ci, jr = jg - HH;
                        float v = accs[ri][ci] + gx[(size_t)b * H3 + jg];
                        float r = sigmoidf_(v);
                        g_hr[b * HH + jr] = r * __ldcg(&hprev[(size_t)b * HH + jr]);
                    }
                }
            }
        }
        grid_barrier();

        // ================= phase 2: cand = (h*r) @ Wh_slice =================
        float q00 = 0, q01 = 0, q10 = 0, q11 = 0;
#pragma unroll
        for (int i = 0; i < 8; i++) {
            int f = tid + STHR * i, b = f >> 4, kq = f & 15;
            pf[i] = ldcg4(g_hr + (size_t)b * HH + kq * 4);
        }
        for (int kt = 0; kt < HH / TK; ++kt) {
#pragma unroll
            for (int i = 0; i < 8; i++) {
                int f = tid + STHR * i, b = f >> 4, kk = (f & 15) * 4;
                h_s[(kk + 0) * HP + b] = pf[i].x;
                h_s[(kk + 1) * HP + b] = pf[i].y;
                h_s[(kk + 2) * HP + b] = pf[i].z;
                h_s[(kk + 3) * HP + b] = pf[i].w;
            }
            __syncthreads();
            if (kt + 1 < HH / TK) {
#pragma unroll
                for (int i = 0; i < 8; i++) {
                    int f = tid + STHR * i, b = f >> 4, kq = f & 15;
                    pf[i] = ldcg4(g_hr + (size_t)b * HH + (kt + 1) * TK + kq * 4);
                }
            }
            const float* wb = Wh_s + kt * TK * HCC;
#pragma unroll 4
            for (int kk = 0; kk < TK; ++kk) {
                float2 hv = *(const float2*)&h_s[kk * HP + p2r0];
                float2 wv = *(const float2*)&wb[kk * HCC + p2c0];
                q00 += hv.x * wv.x; q01 += hv.x * wv.y;
                q10 += hv.y * wv.x; q11 += hv.y * wv.y;
            }
            __syncthreads();
        }
        { // epilogue: h_new = z*h + (1-z)*sigmoid(cand)
            float qa[2][2] = {{q00, q01}, {q10, q11}};
            float* hnew = g_h + (size_t)(t + 1) * BB * HH;
#pragma unroll
            for (int ri = 0; ri < 2; ++ri) {
                int b = p2r0 + ri;
#pragma unroll
                for (int ci = 0; ci < 2; ++ci) {
                    int j = c * HCC + p2c0 + ci;
                    float v = qa[ri][ci] + gx[(size_t)b * H3 + 2 * HH + j];
                    float cand = sigmoidf_(v);
                    float z = __ldcg(&g_z[b * HH + j]);
                    float hp = __ldcg(&hprev[(size_t)b * HH + j]);
                    hnew[(size_t)b * HH + j] = z * hp + (1.f - z) * cand;
                }
            }
        }
        grid_barrier();
    }
}

// ---------------------------------------------------------------------------
extern "C" void kernel_launch(void* const* d_in, const int* in_sizes, int n_in,
                              void* d_out, int out_size)
{
    const float* x  = (const float*)d_in[0];
    const float* Wz = (const float*)d_in[1];
    const float* bz = (const float*)d_in[2];
    const float* Wr = (const float*)d_in[3];
    const float* br = (const float*)d_in[4];
    const float* Wh = (const float*)d_in[5];
    const float* bh = (const float*)d_in[6];
    const float* Wo = (const float*)d_in[7];
    const float* bo = (const float*)d_in[8];
    float* out = (float*)d_out;
    (void)in_sizes; (void)n_in; (void)out_size;

    float *gx = nullptr, *hall = nullptr;
    cudaGetSymbolAddress((void**)&gx, g_gx);
    cudaGetSymbolAddress((void**)&hall, g_h);

    cudaFuncSetAttribute(gru_scan, cudaFuncAttributeMaxDynamicSharedMemorySize, SMEM_SCAN);

    // 1) pre-GEMMs: x-part of gate pre-activations (+bias), K = I = 512
    dim3 gpre(HH / GN, TB / GM); // (16, 256)
    sgemm_bias<<<gpre, GT>>>(x, Wz, bz, gx + 0,      II, II, HH, H3);
    sgemm_bias<<<gpre, GT>>>(x, Wr, br, gx + HH,     II, II, HH, H3);
    sgemm_bias<<<gpre, GT>>>(x, Wh, bh, gx + 2 * HH, II, II, HH, H3);

    // 2) persistent recurrent scan
    gru_scan<<<NCTA, STHR, SMEM_SCAN>>>(Wz, Wr, Wh);

    // 3) post-GEMM: out = h_all @ Wo + bo  (h for output t lives in slot t+1)
    dim3 gpost(OO / GN, TB / GM); // (8, 256)
    sgemm_bias<<<gpost, GT>>>(hall + BB * HH, Wo, bo, out, HH, HH, OO, OO);
}

// round 10
// speedup vs baseline: 2.6297x; 2.6297x over previous
#include <cuda_runtime.h>
#include <cuda_bf16.h>
#include <math.h>

// ---------------------------------------------------------------------------
// TrendsGRU: out[t,b,:] = GRU-scan(x) @ Wo + bo
// T=512, B=64, I=512, H=1024, O=512
//
//   1) pre-GEMM  (fp32): g_gx = x @ [Wz_x|Wr_x|Wh_x] + bias
//   2) persistent scan: recurrent GEMMs on tensor cores (bf16 hi/lo split,
//      3-product mma.sync.m16n8k16, fp32 accumulate), weights prepacked in
//      SMEM in fragment layout, 2 grid barriers/step
//   3) post-GEMM (fp32): out = h_all @ Wo + bo
// ---------------------------------------------------------------------------

#define TT 512
#define BB 64
#define II 512
#define HH 1024
#define OO 512
#define H3 3072
#define TB (TT * BB)

// -------------------------- scratch (device globals) -----------------------
__device__ float g_gx[(size_t)TB * H3];           // gate pre-activations (x part + bias)
__device__ float g_h[(size_t)(TT + 1) * BB * HH]; // h_all fp32, slot 0 = zeros
__device__ float g_z[BB * HH];                    // z gate (current step)
__device__ uint2 g_hb[512 * BB];                  // [kpair][b] (hi2,lo2) bf16 of current h
__device__ uint2 g_hrb[512 * BB];                 // [kpair][b] (hi2,lo2) bf16 of h*r
__device__ unsigned g_barCount;
__device__ unsigned g_barGen;

// ---------------------------------------------------------------------------
// fp32 SGEMM with bias (unchanged from R7): C[M,N] = A[M,K] @ Bw[K,N] + bias
// ---------------------------------------------------------------------------
#define GM 128
#define GN 64
#define GK 16
#define GT 256
#define AP 132
#define BP 68

__global__ __launch_bounds__(GT) void sgemm_bias(
    const float* __restrict__ A, const float* __restrict__ Bw,
    const float* __restrict__ bias, float* __restrict__ C,
    int K, int lda, int ldb, int ldc)
{
    __shared__ float As[GK * AP];
    __shared__ float Bs[GK * BP];

    const int t = threadIdx.x;
    const int m0 = blockIdx.y * GM;
    const int n0 = blockIdx.x * GN;

    const int am0 = t >> 2, akq0 = t & 3;
    const int am1 = (t + GT) >> 2, akq1 = (t + GT) & 3;
    const int bkr = t >> 4, bnq = t & 15;

    const float* Aptr0 = A + (size_t)(m0 + am0) * lda + akq0 * 4;
    const float* Aptr1 = A + (size_t)(m0 + am1) * lda + akq1 * 4;
    const float* Bptr  = Bw + (size_t)bkr * ldb + n0 + bnq * 4;

    const int r0 = (t & 15) * 8;
    const int c0 = (t >> 4) * 4;

    float acc[8][4];
#pragma unroll
    for (int i = 0; i < 8; i++)
#pragma unroll
        for (int j = 0; j < 4; j++) acc[i][j] = 0.f;

    float4 apf0 = *(const float4*)(Aptr0);
    float4 apf1 = *(const float4*)(Aptr1);
    float4 bpf  = *(const float4*)(Bptr);

    const int nkt = K / GK;
    for (int kt = 0; kt < nkt; ++kt) {
        As[(akq0 * 4 + 0) * AP + am0] = apf0.x;
        As[(akq0 * 4 + 1) * AP + am0] = apf0.y;
        As[(akq0 * 4 + 2) * AP + am0] = apf0.z;
        As[(akq0 * 4 + 3) * AP + am0] = apf0.w;
        As[(akq1 * 4 + 0) * AP + am1] = apf1.x;
        As[(akq1 * 4 + 1) * AP + am1] = apf1.y;
        As[(akq1 * 4 + 2) * AP + am1] = apf1.z;
        As[(akq1 * 4 + 3) * AP + am1] = apf1.w;
        *(float4*)&Bs[bkr * BP + bnq * 4] = bpf;
        __syncthreads();

        if (kt + 1 < nkt) {
            apf0 = *(const float4*)(Aptr0 + (kt + 1) * GK);
            apf1 = *(const float4*)(Aptr1 + (kt + 1) * GK);
            bpf  = *(const float4*)(Bptr + (size_t)(kt + 1) * GK * ldb);
        }

#pragma unroll 8
        for (int k = 0; k < GK; k++) {
            const float* ar = &As[k * AP + r0];
            float4 a0 = *(const float4*)(ar);
            float4 a1 = *(const float4*)(ar + 4);
            float4 b4 = *(const float4*)&Bs[k * BP + c0];
            float av[8] = {a0.x, a0.y, a0.z, a0.w, a1.x, a1.y, a1.z, a1.w};
            float bv[4] = {b4.x, b4.y, b4.z, b4.w};
#pragma unroll
            for (int i = 0; i < 8; i++)
#pragma unroll
                for (int j = 0; j < 4; j++) acc[i][j] += av[i] * bv[j];
        }
        __syncthreads();
    }

    float4 bb = *(const float4*)&bias[n0 + c0];
#pragma unroll
    for (int i = 0; i < 8; i++) {
        float4 o = make_float4(acc[i][0] + bb.x, acc[i][1] + bb.y,
                               acc[i][2] + bb.z, acc[i][3] + bb.w);
        *(float4*)&C[(size_t)(m0 + r0 + i) * ldc + n0 + c0] = o;
    }
}

// ---------------------------------------------------------------------------
// Persistent GRU scan kernel — tensor-core (bf16 split) version
// ---------------------------------------------------------------------------
#define NCTA 128
#define STHR 128
#define ZRC 16 // zr columns per CTA (2048/128)
#define HCC 8  // candidate columns per CTA (1024/128)
#define NKS 64 // K=1024 -> 64 mma k-steps of 16
#define HP2 68 // h2 pitch in uint2 (>=64, ==4 mod 16)

#define WZR_U4 (NKS * 2 * 32) // 4096 uint4 (64KB)
#define WH_U4  (NKS * 32)     // 2048 uint4 (32KB)
#define H2_U2  (32 * HP2)     // 2176 uint2 (17KB): one K-tile of 64 (32 kpairs)
#define SMEM_SCAN (WZR_U4 * 16 + WH_U4 * 16 + H2_U2 * 8)

__device__ __forceinline__ float sigmoidf_(float v) { return 1.f / (1.f + __expf(-v)); }
__device__ __forceinline__ float2 ldcg2(const float* p) { return __ldcg((const float2*)p); }

// split (a,b) into bf16 hi pair + bf16 lo (residual) pair, packed as b32
__device__ __forceinline__ void hilo2(float a, float b, unsigned& h, unsigned& l)
{
    __nv_bfloat162 hv = __floats2bfloat162_rn(a, b);
    float ra = a - __bfloat162float(hv.x);
    float rb = b - __bfloat162float(hv.y);
    __nv_bfloat162 lv = __floats2bfloat162_rn(ra, rb);
    h = *reinterpret_cast<unsigned*>(&hv);
    l = *reinterpret_cast<unsigned*>(&lv);
}

__device__ __forceinline__ void mma16816(float* d,
                                         unsigned a0, unsigned a1, unsigned a2, unsigned a3,
                                         unsigned b0, unsigned b1)
{
    asm volatile(
        "mma.sync.aligned.m16n8k16.row.col.f32.bf16.bf16.f32 "
        "{%0,%1,%2,%3},{%4,%5,%6,%7},{%8,%9},{%0,%1,%2,%3};"
        : "+f"(d[0]), "+f"(d[1]), "+f"(d[2]), "+f"(d[3])
        : "r"(a0), "r"(a1), "r"(a2), "r"(a3), "r"(b0), "r"(b1));
}

__device__ __forceinline__ void grid_barrier()
{
    __threadfence();
    __syncthreads();
    if (threadIdx.x == 0) {
        volatile unsigned* genp = &g_barGen;
        unsigned gen = *genp;
        unsigned arrived = atomicAdd(&g_barCount, 1u);
        if (arrived == NCTA - 1) {
            atomicExch(&g_barCount, 0u);
            __threadfence();
            atomicAdd(&g_barGen, 1u);
        } else {
            while (*genp == gen) { __nanosleep(64); }
        }
    }
    __syncthreads();
    __threadfence();
}

__global__ __launch_bounds__(STHR, 1) void gru_scan(
    const float* __restrict__ Wz, const float* __restrict__ Wr,
    const float* __restrict__ Wh)
{
    extern __shared__ unsigned char smraw[];
    uint4* wzr4 = (uint4*)smraw;        // [kstep][nt][lane]: {b0h,b1h,b0l,b1l}
    uint4* wh4  = wzr4 + WZR_U4;        // [kstep][lane]
    uint2* h2   = (uint2*)(wh4 + WH_U4);// [kpair_local 32][b] pitch HP2, (hi2,lo2)

    const int tid = threadIdx.x;
    const int c = blockIdx.x;
    const int lane = tid & 31;
    const int quad = lane & 3;
    const int mrow = (tid >> 5) * 16 + (lane >> 2); // batch row (top half)
    const int q2 = quad * 2;
    const bool isZ = (c < 64);

    // ---- prepack recurrent weight slices into SMEM fragment layout (once) ----
    for (int e = tid; e < NKS * 2 * 32; e += STHR) {
        int kst = e >> 6, nt = (e >> 5) & 1, ln = e & 31;
        int jg = c * ZRC + nt * 8 + (ln >> 2);
        int k0 = kst * 16 + (ln & 3) * 2;
        const float* Wsel;
        int col;
        if (jg < HH) { Wsel = Wz; col = jg; }
        else         { Wsel = Wr; col = jg - HH; }
        float w0 = __ldg(&Wsel[(size_t)(II + k0) * HH + col]);
        float w1 = __ldg(&Wsel[(size_t)(II + k0 + 1) * HH + col]);
        float w8 = __ldg(&Wsel[(size_t)(II + k0 + 8) * HH + col]);
        float w9 = __ldg(&Wsel[(size_t)(II + k0 + 9) * HH + col]);
        unsigned b0h, b0l, b1h, b1l;
        hilo2(w0, w1, b0h, b0l);
        hilo2(w8, w9, b1h, b1l);
        wzr4[e] = make_uint4(b0h, b1h, b0l, b1l);
    }
    for (int e = tid; e < NKS * 32; e += STHR) {
        int kst = e >> 5, ln = e & 31;
        int col = c * HCC + (ln >> 2);
        int k0 = kst * 16 + (ln & 3) * 2;
        float w0 = __ldg(&Wh[(size_t)(II + k0) * HH + col]);
        float w1 = __ldg(&Wh[(size_t)(II + k0 + 1) * HH + col]);
        float w8 = __ldg(&Wh[(size_t)(II + k0 + 8) * HH + col]);
        float w9 = __ldg(&Wh[(size_t)(II + k0 + 9) * HH + col]);
        unsigned b0h, b0l, b1h, b1l;
        hilo2(w0, w1, b0h, b0l);
        hilo2(w8, w9, b1h, b1l);
        wh4[e] = make_uint4(b0h, b1h, b0l, b1l);
    }

    // zero h slot 0 and bf16 h buffer (h0 = 0); redone each launch for determinism
    for (int idx = c * STHR + tid; idx < BB * HH; idx += NCTA * STHR) g_h[idx] = 0.f;
    for (int idx = c * STHR + tid; idx < 512 * BB; idx += NCTA * STHR) g_hb[idx] = make_uint2(0u, 0u);
    grid_barrier();

    const uint4* hb4  = (const uint4*)g_hb;  // [kp][bq(32)]
    const uint4* hrb4 = (const uint4*)g_hrb;

    for (int t = 0; t < TT; ++t) {
        const float* hprev = g_h + (size_t)t * BB * HH;
        const float* gx = g_gx + (size_t)t * BB * H3;

        // ---------- phase-1 epilogue operand prefetch (DRAM-latency hiding) ----------
        float2 p1gx[2][2], p1hp[2][2];
#pragma unroll
        for (int nt = 0; nt < 2; ++nt) {
            int jg = c * ZRC + nt * 8 + q2;
            p1gx[nt][0] = ldcg2(&gx[(size_t)mrow * H3 + jg]);
            p1gx[nt][1] = ldcg2(&gx[(size_t)(mrow + 8) * H3 + jg]);
            if (!isZ) {
                int jr = jg - HH;
                p1hp[nt][0] = ldcg2(&hprev[(size_t)mrow * HH + jr]);
                p1hp[nt][1] = ldcg2(&hprev[(size_t)(mrow + 8) * HH + jr]);
            }
        }

        // ================= phase 1: zr = hprev @ Wzr_slice (tensor cores) ==========
        float acc1[6][4]; // [nt*3 + {hh,hl,lh}][4]
#pragma unroll
        for (int g = 0; g < 6; g++)
#pragma unroll
            for (int i = 0; i < 4; i++) acc1[g][i] = 0.f;

        uint4 pf[8];
#pragma unroll
        for (int i = 0; i < 8; i++) {
            int f = tid + STHR * i, kpl = f >> 5, bq = f & 31;
            pf[i] = __ldcg(&hb4[(size_t)(0 * 32 + kpl) * 32 + bq]);
        }
        for (int kt = 0; kt < 16; ++kt) {
#pragma unroll
            for (int i = 0; i < 8; i++) {
                int f = tid + STHR * i, kpl = f >> 5, bq = f & 31;
                *(uint4*)&h2[kpl * HP2 + bq * 2] = pf[i];
            }
            __syncthreads();
            if (kt + 1 < 16) {
#pragma unroll
                for (int i = 0; i < 8; i++) {
                    int f = tid + STHR * i, kpl = f >> 5, bq = f & 31;
                    pf[i] = __ldcg(&hb4[(size_t)((kt + 1) * 32 + kpl) * 32 + bq]);
                }
            }
#pragma unroll
            for (int ks = 0; ks < 4; ++ks) {
                int kp0 = ks * 8 + quad;
                uint2 u0 = h2[kp0 * HP2 + mrow];
                uint2 u1 = h2[kp0 * HP2 + mrow + 8];
                uint2 u2 = h2[(kp0 + 4) * HP2 + mrow];
                uint2 u3 = h2[(kp0 + 4) * HP2 + mrow + 8];
                int kst = kt * 4 + ks;
                uint4 B0 = wzr4[(kst * 2 + 0) * 32 + lane];
                uint4 B1 = wzr4[(kst * 2 + 1) * 32 + lane];
                mma16816(acc1[0], u0.x, u1.x, u2.x, u3.x, B0.x, B0.y); // hi*hi
                mma16816(acc1[1], u0.x, u1.x, u2.x, u3.x, B0.z, B0.w); // hi*lo
                mma16816(acc1[2], u0.y, u1.y, u2.y, u3.y, B0.x, B0.y); // lo*hi
                mma16816(acc1[3], u0.x, u1.x, u2.x, u3.x, B1.x, B1.y);
                mma16816(acc1[4], u0.x, u1.x, u2.x, u3.x, B1.z, B1.w);
                mma16816(acc1[5], u0.y, u1.y, u2.y, u3.y, B1.x, B1.y);
            }
            __syncthreads();
        }
        // epilogue: add gx, sigmoid, publish z or (h*r) in bf16 hi/lo
#pragma unroll
        for (int nt = 0; nt < 2; ++nt) {
            int jg = c * ZRC + nt * 8 + q2;
            float s0 = acc1[nt * 3][0] + acc1[nt * 3 + 1][0] + acc1[nt * 3 + 2][0];
            float s1 = acc1[nt * 3][1] + acc1[nt * 3 + 1][1] + acc1[nt * 3 + 2][1];
            float s2 = acc1[nt * 3][2] + acc1[nt * 3 + 1][2] + acc1[nt * 3 + 2][2];
            float s3 = acc1[nt * 3][3] + acc1[nt * 3 + 1][3] + acc1[nt * 3 + 2][3];
            if (isZ) {
                float2 zt = make_float2(sigmoidf_(s0 + p1gx[nt][0].x), sigmoidf_(s1 + p1gx[nt][0].y));
                float2 zb = make_float2(sigmoidf_(s2 + p1gx[nt][1].x), sigmoidf_(s3 + p1gx[nt][1].y));
                *(float2*)&g_z[mrow * HH + jg] = zt;
                *(float2*)&g_z[(mrow + 8) * HH + jg] = zb;
            } else {
                int kp = (jg - HH) >> 1;
                float r0 = sigmoidf_(s0 + p1gx[nt][0].x), r1 = sigmoidf_(s1 + p1gx[nt][0].y);
                float r2 = sigmoidf_(s2 + p1gx[nt][1].x), r3 = sigmoidf_(s3 + p1gx[nt][1].y);
                unsigned hh, ll;
                hilo2(r0 * p1hp[nt][0].x, r1 * p1hp[nt][0].y, hh, ll);
                g_hrb[kp * BB + mrow] = make_uint2(hh, ll);
                hilo2(r2 * p1hp[nt][1].x, r3 * p1hp[nt][1].y, hh, ll);
                g_hrb[kp * BB + mrow + 8] = make_uint2(hh, ll);
            }
        }
        grid_barrier();

        // ---------- phase-2 epilogue operand prefetch ----------
        int j = c * HCC + q2;
        float2 p2gx0 = ldcg2(&gx[(size_t)mrow * H3 + 2 * HH + j]);
        float2 p2gx1 = ldcg2(&gx[(size_t)(mrow + 8) * H3 + 2 * HH + j]);
        float2 p2z0 = ldcg2(&g_z[mrow * HH + j]);
        float2 p2z1 = ldcg2(&g_z[(mrow + 8) * HH + j]);
        float2 p2hp0 = ldcg2(&hprev[(size_t)mrow * HH + j]);
        float2 p2hp1 = ldcg2(&hprev[(size_t)(mrow + 8) * HH + j]);

        // ================= phase 2: cand = (h*r) @ Wh_slice ========================
        float acc2[6][4]; // [parity*3 + prod][4]
#pragma unroll
        for (int g = 0; g < 6; g++)
#pragma unroll
            for (int i = 0; i < 4; i++) acc2[g][i] = 0.f;

#pragma unroll
        for (int i = 0; i < 8; i++) {
            int f = tid + STHR * i, kpl = f >> 5, bq = f & 31;
            pf[i] = __ldcg(&hrb4[(size_t)(0 * 32 + kpl) * 32 + bq]);
        }
        for (int kt = 0; kt < 16; ++kt) {
#pragma unroll
            for (int i = 0; i < 8; i++) {
                int f = tid + STHR * i, kpl = f >> 5, bq = f & 31;
                *(uint4*)&h2[kpl * HP2 + bq * 2] = pf[i];
            }
            __syncthreads();
            if (kt + 1 < 16) {
#pragma unroll
                for (int i = 0; i < 8; i++) {
                    int f = tid + STHR * i, kpl = f >> 5, bq = f & 31;
                    pf[i] = __ldcg(&hrb4[(size_t)((kt + 1) * 32 + kpl) * 32 + bq]);
                }
            }
#pragma unroll
            for (int ks = 0; ks < 4; ++ks) {
                int kp0 = ks * 8 + quad;
                uint2 u0 = h2[kp0 * HP2 + mrow];
                uint2 u1 = h2[kp0 * HP2 + mrow + 8];
                uint2 u2 = h2[(kp0 + 4) * HP2 + mrow];
                uint2 u3 = h2[(kp0 + 4) * HP2 + mrow + 8];
                int kst = kt * 4 + ks;
                uint4 Bw = wh4[kst * 32 + lane];
                int g0 = (ks & 1) * 3;
                mma16816(acc2[g0 + 0], u0.x, u1.x, u2.x, u3.x, Bw.x, Bw.y);
                mma16816(acc2[g0 + 1], u0.x, u1.x, u2.x, u3.x, Bw.z, Bw.w);
                mma16816(acc2[g0 + 2], u0.y, u1.y, u2.y, u3.y, Bw.x, Bw.y);
            }
            __syncthreads();
        }
        { // epilogue: h_new = z*h + (1-z)*sigmoid(cand); publish fp32 + bf16 hi/lo
            float s0 = 0, s1 = 0, s2 = 0, s3 = 0;
#pragma unroll
            for (int g = 0; g < 6; g++) {
                s0 += acc2[g][0]; s1 += acc2[g][1]; s2 += acc2[g][2]; s3 += acc2[g][3];
            }
            float c0 = sigmoidf_(s0 + p2gx0.x), c1 = sigmoidf_(s1 + p2gx0.y);
            float c2 = sigmoidf_(s2 + p2gx1.x), c3 = sigmoidf_(s3 + p2gx1.y);
            float hn0 = p2z0.x * p2hp0.x + (1.f - p2z0.x) * c0;
            float hn1 = p2z0.y * p2hp0.y + (1.f - p2z0.y) * c1;
            float hn2 = p2z1.x * p2hp1.x + (1.f - p2z1.x) * c2;
            float hn3 = p2z1.y * p2hp1.y + (1.f - p2z1.y) * c3;
            float* hnew = g_h + (size_t)(t + 1) * BB * HH;
            *(float2*)&hnew[(size_t)mrow * HH + j] = make_float2(hn0, hn1);
            *(float2*)&hnew[(size_t)(mrow + 8) * HH + j] = make_float2(hn2, hn3);
            int kp = j >> 1;
            unsigned hh, ll;
            hilo2(hn0, hn1, hh, ll);
            g_hb[kp * BB + mrow] = make_uint2(hh, ll);
            hilo2(hn2, hn3, hh, ll);
            g_hb[kp * BB + mrow + 8] = make_uint2(hh, ll);
        }
        grid_barrier();
    }
}

// ---------------------------------------------------------------------------
extern "C" void kernel_launch(void* const* d_in, const int* in_sizes, int n_in,
                              void* d_out, int out_size)
{
    const float* x  = (const float*)d_in[0];
    const float* Wz = (const float*)d_in[1];
    const float* bz = (const float*)d_in[2];
    const float* Wr = (const float*)d_in[3];
    const float* br = (const float*)d_in[4];
    const float* Wh = (const float*)d_in[5];
    const float* bh = (const float*)d_in[6];
    const float* Wo = (const float*)d_in[7];
    const float* bo = (const float*)d_in[8];
    float* out = (float*)d_out;
    (void)in_sizes; (void)n_in; (void)out_size;

    float *gx = nullptr, *hall = nullptr;
    cudaGetSymbolAddress((void**)&gx, g_gx);
    cudaGetSymbolAddress((void**)&hall, g_h);

    cudaFuncSetAttribute(gru_scan, cudaFuncAttributeMaxDynamicSharedMemorySize, SMEM_SCAN);

    // 1) pre-GEMMs: x-part of gate pre-activations (+bias), K = I = 512
    dim3 gpre(HH / GN, TB / GM); // (16, 256)
    sgemm_bias<<<gpre, GT>>>(x, Wz, bz, gx + 0,      II, II, HH, H3);
    sgemm_bias<<<gpre, GT>>>(x, Wr, br, gx + HH,     II, II, HH, H3);
    sgemm_bias<<<gpre, GT>>>(x, Wh, bh, gx + 2 * HH, II, II, HH, H3);

    // 2) persistent recurrent scan (tensor cores)
    gru_scan<<<NCTA, STHR, SMEM_SCAN>>>(Wz, Wr, Wh);

    // 3) post-GEMM: out = h_all @ Wo + bo  (h for output t lives in slot t+1)
    dim3 gpost(OO / GN, TB / GM); // (8, 256)
    sgemm_bias<<<gpost, GT>>>(hall + BB * HH, Wo, bo, out, HH, HH, OO, OO);
}

// round 11
// speedup vs baseline: 3.5197x; 1.3385x over previous
#include <cuda_runtime.h>
#include <cuda_bf16.h>
#include <math.h>

// ---------------------------------------------------------------------------
// TrendsGRU: out[t,b,:] = GRU-scan(x) @ Wo + bo
// T=512, B=64, I=512, H=1024, O=512
//
//   0) pack kernels: W (x-part) and Wo -> bf16 hi/lo mma B-fragment arrays
//   1) pre-GEMM  (tensor, hi/lo bf16 3-product): g_gx = x @ [Wz|Wr|Wh]_x + b
//   2) persistent scan: A-fragments direct from global (no smem staging,
//      no syncthreads in GEMM), B-fragments prepacked in smem,
//      flag-based grid barrier, 2 barriers/step
//   3) post-GEMM (tensor): out = h_all @ Wo + bo
// ---------------------------------------------------------------------------

#define TT 512
#define BB 64
#define II 512
#define HH 1024
#define OO 512
#define H3 3072
#define TB (TT * BB)
#define NCTA 128
#define STHR 128

// -------------------------- scratch (device globals) -----------------------
__device__ float g_gx[(size_t)TB * H3];           // gate pre-activations (x part + bias)
__device__ float g_h[(size_t)(TT + 1) * BB * HH]; // h_all fp32, slot 0 = zeros
__device__ float g_z[BB * HH];                    // z gate (current step)
__device__ uint2 g_hb[512 * BB];                  // [kpair][b] (hi2,lo2) bf16 of current h
__device__ uint2 g_hrb[512 * BB];                 // [kpair][b] (hi2,lo2) bf16 of h*r
__device__ unsigned g_barCount;                   // init barrier (gen-based)
__device__ unsigned g_barGen;
__device__ unsigned g_flag[NCTA * 8];             // padded per-CTA progress flags

// W fragment arrays (packed once per launch)
__device__ uint4 g_wfz[(II / 16) * (HH / 8) * 32]; // 32*128*32
__device__ uint4 g_wfr[(II / 16) * (HH / 8) * 32];
__device__ uint4 g_wfh[(II / 16) * (HH / 8) * 32];
__device__ uint4 g_wfo[(HH / 16) * (OO / 8) * 32]; // 64*64*32

// ---------------------------------------------------------------------------
// common helpers
// ---------------------------------------------------------------------------
__device__ __forceinline__ float sigmoidf_(float v) { return 1.f / (1.f + __expf(-v)); }
__device__ __forceinline__ float2 ldcg2(const float* p) { return __ldcg((const float2*)p); }

// split (a,b) into bf16 hi pair + bf16 lo (residual) pair, packed as b32
__device__ __forceinline__ void hilo2(float a, float b, unsigned& h, unsigned& l)
{
    __nv_bfloat162 hv = __floats2bfloat162_rn(a, b);
    float ra = a - __bfloat162float(hv.x);
    float rb = b - __bfloat162float(hv.y);
    __nv_bfloat162 lv = __floats2bfloat162_rn(ra, rb);
    h = *reinterpret_cast<unsigned*>(&hv);
    l = *reinterpret_cast<unsigned*>(&lv);
}

__device__ __forceinline__ void mma16816(float* d,
                                         unsigned a0, unsigned a1, unsigned a2, unsigned a3,
                                         unsigned b0, unsigned b1)
{
    asm volatile(
        "mma.sync.aligned.m16n8k16.row.col.f32.bf16.bf16.f32 "
        "{%0,%1,%2,%3},{%4,%5,%6,%7},{%8,%9},{%0,%1,%2,%3};"
        : "+f"(d[0]), "+f"(d[1]), "+f"(d[2]), "+f"(d[3])
        : "r"(a0), "r"(a1), "r"(a2), "r"(a3), "r"(b0), "r"(b1));
}

// ---------------------------------------------------------------------------
// pack kernel: W fp32 [K][N] (row-major, N contiguous) -> B-fragment uint4s
// out[(ks*ntiles + nt)*32 + lane] = {b0h, b1h, b0l, b1l}
//   b0 = W[ks*16 + q*2 .. +1][nt*8 + (lane>>2)], b1 = rows +8
// ---------------------------------------------------------------------------
__global__ void pack_wfrag(const float* __restrict__ W, uint4* __restrict__ out,
                           int K, int N)
{
    int e = blockIdx.x * blockDim.x + threadIdx.x;
    int total = (K / 16) * (N / 8) * 32;
    if (e >= total) return;
    int lane = e & 31;
    int nt = (e >> 5) % (N / 8);
    int ks = (e >> 5) / (N / 8);
    int col = nt * 8 + (lane >> 2);
    int k0 = ks * 16 + (lane & 3) * 2;
    float w0 = __ldg(&W[(size_t)k0 * N + col]);
    float w1 = __ldg(&W[(size_t)(k0 + 1) * N + col]);
    float w8 = __ldg(&W[(size_t)(k0 + 8) * N + col]);
    float w9 = __ldg(&W[(size_t)(k0 + 9) * N + col]);
    unsigned b0h, b0l, b1h, b1l;
    hilo2(w0, w1, b0h, b0l);
    hilo2(w8, w9, b1h, b1l);
    out[e] = make_uint4(b0h, b1h, b0l, b1l);
}

// ---------------------------------------------------------------------------
// Tensor-core GEMM with bias: C[M,N] = A[M,K] @ W[K,N] + bias[N]
// A fp32 (row-major, lda), W prepacked fragments (ntilesTot = Nfull/8),
// CTA tile 128x64, 8 warps (one m16 row-block each), acc fp32.
// ---------------------------------------------------------------------------
__global__ __launch_bounds__(256, 2) void mma_gemm_bias(
    const float* __restrict__ A, const uint4* __restrict__ Wf,
    const float* __restrict__ bias, float* __restrict__ C,
    int K, int lda, int ntilesTot, int ldc)
{
    const int w = threadIdx.x >> 5;
    const int lane = threadIdx.x & 31;
    const int r = lane >> 2, q = lane & 3;
    const int mrow = blockIdx.y * 128 + w * 16 + r;
    const int nt0 = blockIdx.x * 8;

    const float* Arow0 = A + (size_t)mrow * lda + q * 2;
    const float* Arow1 = Arow0 + (size_t)8 * lda;

    float acc[8][4];
#pragma unroll
    for (int n = 0; n < 8; n++)
#pragma unroll
        for (int i = 0; i < 4; i++) acc[n][i] = 0.f;

    const int KS = K / 16;
#pragma unroll 2
    for (int ks = 0; ks < KS; ++ks) {
        float2 a0 = *(const float2*)(Arow0 + ks * 16);
        float2 a1 = *(const float2*)(Arow1 + ks * 16);
        float2 a2 = *(const float2*)(Arow0 + ks * 16 + 8);
        float2 a3 = *(const float2*)(Arow1 + ks * 16 + 8);
        unsigned a0h, a0l, a1h, a1l, a2h, a2l, a3h, a3l;
        hilo2(a0.x, a0.y, a0h, a0l);
        hilo2(a1.x, a1.y, a1h, a1l);
        hilo2(a2.x, a2.y, a2h, a2l);
        hilo2(a3.x, a3.y, a3h, a3l);
        const uint4* bp = Wf + ((size_t)ks * ntilesTot + nt0) * 32 + lane;
#pragma unroll
        for (int nt = 0; nt < 8; ++nt) {
            uint4 B = __ldg(&bp[nt * 32]);
            mma16816(acc[nt], a0h, a1h, a2h, a3h, B.x, B.y); // hi*hi
            mma16816(acc[nt], a0h, a1h, a2h, a3h, B.z, B.w); // hi*lo
            mma16816(acc[nt], a0l, a1l, a2l, a3l, B.x, B.y); // lo*hi
        }
    }

#pragma unroll
    for (int nt = 0; nt < 8; ++nt) {
        int col0 = (nt0 + nt) * 8 + q * 2;
        float2 bb = *(const float2*)&bias[col0];
        *(float2*)&C[(size_t)mrow * ldc + col0] =
            make_float2(acc[nt][0] + bb.x, acc[nt][1] + bb.y);
        *(float2*)&C[(size_t)(mrow + 8) * ldc + col0] =
            make_float2(acc[nt][2] + bb.x, acc[nt][3] + bb.y);
    }
}

// ---------------------------------------------------------------------------
// Persistent GRU scan kernel
// ---------------------------------------------------------------------------
#define ZRC 16 // zr columns per CTA (2048/128)
#define HCC 8  // candidate columns per CTA (1024/128)
#define NKS 64 // K=1024 -> 64 mma k-steps of 16
#define PD 8   // A-fragment software-pipeline depth

#define WZR_U4 (NKS * 2 * 32) // 4096 uint4 (64KB)
#define WH_U4  (NKS * 32)     // 2048 uint4 (32KB)
#define SMEM_SCAN ((WZR_U4 + WH_U4) * 16)

// init-only barrier (gen-based; correct across graph replays)
__device__ __forceinline__ void grid_barrier_init()
{
    __threadfence();
    __syncthreads();
    if (threadIdx.x == 0) {
        volatile unsigned* genp = &g_barGen;
        unsigned gen = *genp;
        unsigned arrived = atomicAdd(&g_barCount, 1u);
        if (arrived == NCTA - 1) {
            atomicExch(&g_barCount, 0u);
            __threadfence();
            atomicAdd(&g_barGen, 1u);
        } else {
            while (*genp == gen) { __nanosleep(64); }
        }
    }
    __syncthreads();
    __threadfence();
}

// steady-state barrier: per-CTA flags, monotonic per-launch targets,
// all 128 threads poll the 128 flags in parallel
__device__ __forceinline__ void flag_barrier(int c, unsigned target)
{
    __threadfence();
    __syncthreads();
    if (threadIdx.x == 0)
        *(volatile unsigned*)&g_flag[c * 8] = target;
    volatile unsigned* fp = &g_flag[threadIdx.x * 8];
    while (*fp < target) { __nanosleep(64); }
    __syncthreads();
    __threadfence();
}

__global__ __launch_bounds__(STHR, 1) void gru_scan(
    const float* __restrict__ Wz, const float* __restrict__ Wr,
    const float* __restrict__ Wh)
{
    extern __shared__ unsigned char smraw[];
    uint4* wzr4 = (uint4*)smraw; // [kstep][nt][lane]: {b0h,b1h,b0l,b1l}
    uint4* wh4  = wzr4 + WZR_U4; // [kstep][lane]

    const int tid = threadIdx.x;
    const int c = blockIdx.x;
    const int lane = tid & 31;
    const int quad = lane & 3;
    const int mrow = (tid >> 5) * 16 + (lane >> 2);
    const int q2 = quad * 2;
    const bool isZ = (c < 64);

    // zero this CTA's flag before the init barrier
    if (tid == 0) *(volatile unsigned*)&g_flag[c * 8] = 0u;

    // ---- prepack recurrent weight slices into SMEM fragment layout (once) ----
    for (int e = tid; e < NKS * 2 * 32; e += STHR) {
        int kst = e >> 6, nt = (e >> 5) & 1, ln = e & 31;
        int jg = c * ZRC + nt * 8 + (ln >> 2);
        int k0 = kst * 16 + (ln & 3) * 2;
        const float* Wsel;
        int col;
        if (jg < HH) { Wsel = Wz; col = jg; }
        else         { Wsel = Wr; col = jg - HH; }
        float w0 = __ldg(&Wsel[(size_t)(II + k0) * HH + col]);
        float w1 = __ldg(&Wsel[(size_t)(II + k0 + 1) * HH + col]);
        float w8 = __ldg(&Wsel[(size_t)(II + k0 + 8) * HH + col]);
        float w9 = __ldg(&Wsel[(size_t)(II + k0 + 9) * HH + col]);
        unsigned b0h, b0l, b1h, b1l;
        hilo2(w0, w1, b0h, b0l);
        hilo2(w8, w9, b1h, b1l);
        wzr4[e] = make_uint4(b0h, b1h, b0l, b1l);
    }
    for (int e = tid; e < NKS * 32; e += STHR) {
        int kst = e >> 5, ln = e & 31;
        int col = c * HCC + (ln >> 2);
        int k0 = kst * 16 + (ln & 3) * 2;
        float w0 = __ldg(&Wh[(size_t)(II + k0) * HH + col]);
        float w1 = __ldg(&Wh[(size_t)(II + k0 + 1) * HH + col]);
        float w8 = __ldg(&Wh[(size_t)(II + k0 + 8) * HH + col]);
        float w9 = __ldg(&Wh[(size_t)(II + k0 + 9) * HH + col]);
        unsigned b0h, b0l, b1h, b1l;
        hilo2(w0, w1, b0h, b0l);
        hilo2(w8, w9, b1h, b1l);
        wh4[e] = make_uint4(b0h, b1h, b0l, b1l);
    }

    // zero h slot 0 and bf16 h buffer (h0 = 0); redone each launch
    for (int idx = c * STHR + tid; idx < BB * HH; idx += NCTA * STHR) g_h[idx] = 0.f;
    for (int idx = c * STHR + tid; idx < 512 * BB; idx += NCTA * STHR) g_hb[idx] = make_uint2(0u, 0u);
    grid_barrier_init();

    // per-lane base pointer into [kp][b] arrays: element (kp0, mrow) = base + ks*512
    const uint2* hbB  = g_hb  + (size_t)quad * BB + mrow;
    const uint2* hrbB = g_hrb + (size_t)quad * BB + mrow;

#define LOADA(src, ks, j)                                        \
    do {                                                         \
        const uint2* _p = (src) + (size_t)(ks) * (8 * BB);       \
        A0[j] = __ldcg(_p);                                      \
        A1[j] = __ldcg(_p + 8);                                  \
        A2[j] = __ldcg(_p + 4 * BB);                             \
        A3[j] = __ldcg(_p + 4 * BB + 8);                         \
    } while (0)

    unsigned bt = 0; // barrier target counter (per launch)

    for (int t = 0; t < TT; ++t) {
        const float* hprev = g_h + (size_t)t * BB * HH;
        const float* gx = g_gx + (size_t)t * BB * H3;

        // ---------- phase-1 epilogue operand prefetch ----------
        float2 p1gx[2][2], p1hp[2][2];
#pragma unroll
        for (int nt = 0; nt < 2; ++nt) {
            int jg = c * ZRC + nt * 8 + q2;
            p1gx[nt][0] = ldcg2(&gx[(size_t)mrow * H3 + jg]);
            p1gx[nt][1] = ldcg2(&gx[(size_t)(mrow + 8) * H3 + jg]);
            if (!isZ) {
                int jr = jg - HH;
                p1hp[nt][0] = ldcg2(&hprev[(size_t)mrow * HH + jr]);
                p1hp[nt][1] = ldcg2(&hprev[(size_t)(mrow + 8) * HH + jr]);
            }
        }

        // ================= phase 1: zr = hprev @ Wzr_slice ==================
        float acc1[6][4];
#pragma unroll
        for (int g = 0; g < 6; g++)
#pragma unroll
            for (int i = 0; i < 4; i++) acc1[g][i] = 0.f;

        {
            uint2 A0[PD], A1[PD], A2[PD], A3[PD];
#pragma unroll
            for (int j = 0; j < PD; ++j) LOADA(hbB, j, j);
#pragma unroll 1
            for (int ks8 = 0; ks8 < NKS; ks8 += PD) {
#pragma unroll
                for (int j = 0; j < PD; ++j) {
                    int ks = ks8 + j;
                    uint2 u0 = A0[j], u1 = A1[j], u2 = A2[j], u3 = A3[j];
                    if (ks8 + PD < NKS) LOADA(hbB, ks + PD, j);
                    uint4 B0 = wzr4[(ks * 2 + 0) * 32 + lane];
                    uint4 B1 = wzr4[(ks * 2 + 1) * 32 + lane];
                    mma16816(acc1[0], u0.x, u1.x, u2.x, u3.x, B0.x, B0.y);
                    mma16816(acc1[1], u0.x, u1.x, u2.x, u3.x, B0.z, B0.w);
                    mma16816(acc1[2], u0.y, u1.y, u2.y, u3.y, B0.x, B0.y);
                    mma16816(acc1[3], u0.x, u1.x, u2.x, u3.x, B1.x, B1.y);
                    mma16816(acc1[4], u0.x, u1.x, u2.x, u3.x, B1.z, B1.w);
                    mma16816(acc1[5], u0.y, u1.y, u2.y, u3.y, B1.x, B1.y);
                }
            }
        }
        // epilogue: add gx, sigmoid, publish z or (h*r) in bf16 hi/lo
#pragma unroll
        for (int nt = 0; nt < 2; ++nt) {
            int jg = c * ZRC + nt * 8 + q2;
            float s0 = acc1[nt * 3][0] + acc1[nt * 3 + 1][0] + acc1[nt * 3 + 2][0];
            float s1 = acc1[nt * 3][1] + acc1[nt * 3 + 1][1] + acc1[nt * 3 + 2][1];
            float s2 = acc1[nt * 3][2] + acc1[nt * 3 + 1][2] + acc1[nt * 3 + 2][2];
            float s3 = acc1[nt * 3][3] + acc1[nt * 3 + 1][3] + acc1[nt * 3 + 2][3];
            if (isZ) {
                float2 zt = make_float2(sigmoidf_(s0 + p1gx[nt][0].x), sigmoidf_(s1 + p1gx[nt][0].y));
                float2 zb = make_float2(sigmoidf_(s2 + p1gx[nt][1].x), sigmoidf_(s3 + p1gx[nt][1].y));
                *(float2*)&g_z[mrow * HH + jg] = zt;
                *(float2*)&g_z[(mrow + 8) * HH + jg] = zb;
            } else {
                int kp = (jg - HH) >> 1;
                float r0 = sigmoidf_(s0 + p1gx[nt][0].x), r1 = sigmoidf_(s1 + p1gx[nt][0].y);
                float r2 = sigmoidf_(s2 + p1gx[nt][1].x), r3 = sigmoidf_(s3 + p1gx[nt][1].y);
                unsigned hh, ll;
                hilo2(r0 * p1hp[nt][0].x, r1 * p1hp[nt][0].y, hh, ll);
                g_hrb[kp * BB + mrow] = make_uint2(hh, ll);
                hilo2(r2 * p1hp[nt][1].x, r3 * p1hp[nt][1].y, hh, ll);
                g_hrb[kp * BB + mrow + 8] = make_uint2(hh, ll);
            }
        }
        flag_barrier(c, ++bt);

        // ---------- phase-2 epilogue operand prefetch ----------
        int j = c * HCC + q2;
        float2 p2gx0 = ldcg2(&gx[(size_t)mrow * H3 + 2 * HH + j]);
        float2 p2gx1 = ldcg2(&gx[(size_t)(mrow + 8) * H3 + 2 * HH + j]);
        float2 p2z0 = ldcg2(&g_z[mrow * HH + j]);
        float2 p2z1 = ldcg2(&g_z[(mrow + 8) * HH + j]);
        float2 p2hp0 = ldcg2(&hprev[(size_t)mrow * HH + j]);
        float2 p2hp1 = ldcg2(&hprev[(size_t)(mrow + 8) * HH + j]);

        // ================= phase 2: cand = (h*r) @ Wh_slice =================
        float acc2[6][4];
#pragma unroll
        for (int g = 0; g < 6; g++)
#pragma unroll
            for (int i = 0; i < 4; i++) acc2[g][i] = 0.f;

        {
            uint2 A0[PD], A1[PD], A2[PD], A3[PD];
#pragma unroll
            for (int jj = 0; jj < PD; ++jj) LOADA(hrbB, jj, jj);
#pragma unroll 1
            for (int ks8 = 0; ks8 < NKS; ks8 += PD) {
#pragma unroll
                for (int jj = 0; jj < PD; ++jj) {
                    int ks = ks8 + jj;
                    uint2 u0 = A0[jj], u1 = A1[jj], u2 = A2[jj], u3 = A3[jj];
                    if (ks8 + PD < NKS) LOADA(hrbB, ks + PD, jj);
                    uint4 Bw = wh4[ks * 32 + lane];
                    int g0 = (ks & 1) * 3;
                    mma16816(acc2[g0 + 0], u0.x, u1.x, u2.x, u3.x, Bw.x, Bw.y);
                    mma16816(acc2[g0 + 1], u0.x, u1.x, u2.x, u3.x, Bw.z, Bw.w);
                    mma16816(acc2[g0 + 2], u0.y, u1.y, u2.y, u3.y, Bw.x, Bw.y);
                }
            }
        }
        { // epilogue: h_new = z*h + (1-z)*sigmoid(cand)
            float s0 = 0, s1 = 0, s2 = 0, s3 = 0;
#pragma unroll
            for (int g = 0; g < 6; g++) {
                s0 += acc2[g][0]; s1 += acc2[g][1]; s2 += acc2[g][2]; s3 += acc2[g][3];
            }
            float c0 = sigmoidf_(s0 + p2gx0.x), c1 = sigmoidf_(s1 + p2gx0.y);
            float c2 = sigmoidf_(s2 + p2gx1.x), c3 = sigmoidf_(s3 + p2gx1.y);
            float hn0 = p2z0.x * p2hp0.x + (1.f - p2z0.x) * c0;
            float hn1 = p2z0.y * p2hp0.y + (1.f - p2z0.y) * c1;
            float hn2 = p2z1.x * p2hp1.x + (1.f - p2z1.x) * c2;
            float hn3 = p2z1.y * p2hp1.y + (1.f - p2z1.y) * c3;
            float* hnew = g_h + (size_t)(t + 1) * BB * HH;
            *(float2*)&hnew[(size_t)mrow * HH + j] = make_float2(hn0, hn1);
            *(float2*)&hnew[(size_t)(mrow + 8) * HH + j] = make_float2(hn2, hn3);
            int kp = j >> 1;
            unsigned hh, ll;
            hilo2(hn0, hn1, hh, ll);
            g_hb[kp * BB + mrow] = make_uint2(hh, ll);
            hilo2(hn2, hn3, hh, ll);
            g_hb[kp * BB + mrow + 8] = make_uint2(hh, ll);
        }
        flag_barrier(c, ++bt);
    }
#undef LOADA
}

// ---------------------------------------------------------------------------
extern "C" void kernel_launch(void* const* d_in, const int* in_sizes, int n_in,
                              void* d_out, int out_size)
{
    const float* x  = (const float*)d_in[0];
    const float* Wz = (const float*)d_in[1];
    const float* bz = (const float*)d_in[2];
    const float* Wr = (const float*)d_in[3];
    const float* br = (const float*)d_in[4];
    const float* Wh = (const float*)d_in[5];
    const float* bh = (const float*)d_in[6];
    const float* Wo = (const float*)d_in[7];
    const float* bo = (const float*)d_in[8];
    float* out = (float*)d_out;
    (void)in_sizes; (void)n_in; (void)out_size;

    float *gx = nullptr, *hall = nullptr;
    uint4 *wfz = nullptr, *wfr = nullptr, *wfh = nullptr, *wfo = nullptr;
    cudaGetSymbolAddress((void**)&gx, g_gx);
    cudaGetSymbolAddress((void**)&hall, g_h);
    cudaGetSymbolAddress((void**)&wfz, g_wfz);
    cudaGetSymbolAddress((void**)&wfr, g_wfr);
    cudaGetSymbolAddress((void**)&wfh, g_wfh);
    cudaGetSymbolAddress((void**)&wfo, g_wfo);

    cudaFuncSetAttribute(gru_scan, cudaFuncAttributeMaxDynamicSharedMemorySize, SMEM_SCAN);

    // 0) pack W x-part fragments (rows 0..I-1 of Wz/Wr/Wh) and Wo fragments
    int preTot = (II / 16) * (HH / 8) * 32;  // 131072
    int postTot = (HH / 16) * (OO / 8) * 32; // 131072
    pack_wfrag<<<(preTot + 255) / 256, 256>>>(Wz, wfz, II, HH);
    pack_wfrag<<<(preTot + 255) / 256, 256>>>(Wr, wfr, II, HH);
    pack_wfrag<<<(preTot + 255) / 256, 256>>>(Wh, wfh, II, HH);
    pack_wfrag<<<(postTot + 255) / 256, 256>>>(Wo, wfo, HH, OO);

    // 1) pre-GEMMs: g_gx[:, gate] = x @ Wgate_x + bgate   (K=I=512)
    dim3 gpre(HH / 64, TB / 128); // (16, 256)
    mma_gemm_bias<<<gpre, 256>>>(x, wfz, bz, gx + 0,      II, II, HH / 8, H3);
    mma_gemm_bias<<<gpre, 256>>>(x, wfr, br, gx + HH,     II, II, HH / 8, H3);
    mma_gemm_bias<<<gpre, 256>>>(x, wfh, bh, gx + 2 * HH, II, II, HH / 8, H3);

    // 2) persistent recurrent scan (tensor cores, no smem staging)
    gru_scan<<<NCTA, STHR, SMEM_SCAN>>>(Wz, Wr, Wh);

    // 3) post-GEMM: out = h_all @ Wo + bo  (h for output t lives in slot t+1)
    dim3 gpost(OO / 64, TB / 128); // (8, 256)
    mma_gemm_bias<<<gpost, 256>>>(hall + BB * HH, wfo, bo, out, HH, HH, OO / 8, OO);
}

// round 12
// speedup vs baseline: 3.7948x; 1.0781x over previous
#include <cuda_runtime.h>
#include <cuda_bf16.h>
#include <math.h>

// ---------------------------------------------------------------------------
// TrendsGRU: out[t,b,:] = GRU-scan(x) @ Wo + bo
// T=512, B=64, I=512, H=1024, O=512
//
//   0) pack kernels: W (x-part) and Wo -> bf16 hi/lo mma B-fragment arrays
//   1) pre-GEMM  (tensor, hi/lo bf16 3-product): g_gx = x @ [Wz|Wr|Wh]_x + b
//   2) persistent scan: 512 thr/CTA, 4-way K-split across warp groups
//      (4 warps/SMSP for latency hiding), smem partial reduction,
//      A-fragments direct from global, B-fragments prepacked in smem,
//      flag-based grid barrier, 2 barriers/step
//   3) post-GEMM (tensor): out = h_all @ Wo + bo
// ---------------------------------------------------------------------------

#define TT 512
#define BB 64
#define II 512
#define HH 1024
#define OO 512
#define H3 3072
#define TB (TT * BB)
#define NCTA 128
#define STHR 512

// -------------------------- scratch (device globals) -----------------------
__device__ float g_gx[(size_t)TB * H3];           // gate pre-activations (x part + bias)
__device__ float g_h[(size_t)(TT + 1) * BB * HH]; // h_all fp32, slot 0 = zeros
__device__ float g_z[BB * HH];                    // z gate (current step)
__device__ uint2 g_hb[512 * BB];                  // [kpair][b] (hi2,lo2) bf16 of current h
__device__ uint2 g_hrb[512 * BB];                 // [kpair][b] (hi2,lo2) bf16 of h*r
__device__ unsigned g_barCount;                   // init barrier (gen-based)
__device__ unsigned g_barGen;
__device__ unsigned g_flag[NCTA * 8];             // padded per-CTA progress flags

// W fragment arrays (packed once per launch)
__device__ uint4 g_wfz[(II / 16) * (HH / 8) * 32];
__device__ uint4 g_wfr[(II / 16) * (HH / 8) * 32];
__device__ uint4 g_wfh[(II / 16) * (HH / 8) * 32];
__device__ uint4 g_wfo[(HH / 16) * (OO / 8) * 32];

// ---------------------------------------------------------------------------
// common helpers
// ---------------------------------------------------------------------------
__device__ __forceinline__ float sigmoidf_(float v) { return 1.f / (1.f + __expf(-v)); }
__device__ __forceinline__ float2 ldcg2(const float* p) { return __ldcg((const float2*)p); }

__device__ __forceinline__ void hilo2(float a, float b, unsigned& h, unsigned& l)
{
    __nv_bfloat162 hv = __floats2bfloat162_rn(a, b);
    float ra = a - __bfloat162float(hv.x);
    float rb = b - __bfloat162float(hv.y);
    __nv_bfloat162 lv = __floats2bfloat162_rn(ra, rb);
    h = *reinterpret_cast<unsigned*>(&hv);
    l = *reinterpret_cast<unsigned*>(&lv);
}

__device__ __forceinline__ void mma16816(float* d,
                                         unsigned a0, unsigned a1, unsigned a2, unsigned a3,
                                         unsigned b0, unsigned b1)
{
    asm volatile(
        "mma.sync.aligned.m16n8k16.row.col.f32.bf16.bf16.f32 "
        "{%0,%1,%2,%3},{%4,%5,%6,%7},{%8,%9},{%0,%1,%2,%3};"
        : "+f"(d[0]), "+f"(d[1]), "+f"(d[2]), "+f"(d[3])
        : "r"(a0), "r"(a1), "r"(a2), "r"(a3), "r"(b0), "r"(b1));
}

// ---------------------------------------------------------------------------
// pack kernel: W fp32 [K][N] -> B-fragment uint4s
// ---------------------------------------------------------------------------
__global__ void pack_wfrag(const float* __restrict__ W, uint4* __restrict__ out,
                           int K, int N)
{
    int e = blockIdx.x * blockDim.x + threadIdx.x;
    int total = (K / 16) * (N / 8) * 32;
    if (e >= total) return;
    int lane = e & 31;
    int nt = (e >> 5) % (N / 8);
    int ks = (e >> 5) / (N / 8);
    int col = nt * 8 + (lane >> 2);
    int k0 = ks * 16 + (lane & 3) * 2;
    float w0 = __ldg(&W[(size_t)k0 * N + col]);
    float w1 = __ldg(&W[(size_t)(k0 + 1) * N + col]);
    float w8 = __ldg(&W[(size_t)(k0 + 8) * N + col]);
    float w9 = __ldg(&W[(size_t)(k0 + 9) * N + col]);
    unsigned b0h, b0l, b1h, b1l;
    hilo2(w0, w1, b0h, b0l);
    hilo2(w8, w9, b1h, b1l);
    out[e] = make_uint4(b0h, b1h, b0l, b1l);
}

// ---------------------------------------------------------------------------
// Tensor-core GEMM with bias (unchanged from R11)
// ---------------------------------------------------------------------------
__global__ __launch_bounds__(256, 2) void mma_gemm_bias(
    const float* __restrict__ A, const uint4* __restrict__ Wf,
    const float* __restrict__ bias, float* __restrict__ C,
    int K, int lda, int ntilesTot, int ldc)
{
    const int w = threadIdx.x >> 5;
    const int lane = threadIdx.x & 31;
    const int r = lane >> 2, q = lane & 3;
    const int mrow = blockIdx.y * 128 + w * 16 + r;
    const int nt0 = blockIdx.x * 8;

    const float* Arow0 = A + (size_t)mrow * lda + q * 2;
    const float* Arow1 = Arow0 + (size_t)8 * lda;

    float acc[8][4];
#pragma unroll
    for (int n = 0; n < 8; n++)
#pragma unroll
        for (int i = 0; i < 4; i++) acc[n][i] = 0.f;

    const int KS = K / 16;
#pragma unroll 2
    for (int ks = 0; ks < KS; ++ks) {
        float2 a0 = *(const float2*)(Arow0 + ks * 16);
        float2 a1 = *(const float2*)(Arow1 + ks * 16);
        float2 a2 = *(const float2*)(Arow0 + ks * 16 + 8);
        float2 a3 = *(const float2*)(Arow1 + ks * 16 + 8);
        unsigned a0h, a0l, a1h, a1l, a2h, a2l, a3h, a3l;
        hilo2(a0.x, a0.y, a0h, a0l);
        hilo2(a1.x, a1.y, a1h, a1l);
        hilo2(a2.x, a2.y, a2h, a2l);
        hilo2(a3.x, a3.y, a3h, a3l);
        const uint4* bp = Wf + ((size_t)ks * ntilesTot + nt0) * 32 + lane;
#pragma unroll
        for (int nt = 0; nt < 8; ++nt) {
            uint4 B = __ldg(&bp[nt * 32]);
            mma16816(acc[nt], a0h, a1h, a2h, a3h, B.x, B.y);
            mma16816(acc[nt], a0h, a1h, a2h, a3h, B.z, B.w);
            mma16816(acc[nt], a0l, a1l, a2l, a3l, B.x, B.y);
        }
    }

#pragma unroll
    for (int nt = 0; nt < 8; ++nt) {
        int col0 = (nt0 + nt) * 8 + q * 2;
        float2 bb = *(const float2*)&bias[col0];
        *(float2*)&C[(size_t)mrow * ldc + col0] =
            make_float2(acc[nt][0] + bb.x, acc[nt][1] + bb.y);
        *(float2*)&C[(size_t)(mrow + 8) * ldc + col0] =
            make_float2(acc[nt][2] + bb.x, acc[nt][3] + bb.y);
    }
}

// ---------------------------------------------------------------------------
// Persistent GRU scan kernel — 512 threads, 4-way K-split
// ---------------------------------------------------------------------------
#define ZRC 16 // zr columns per CTA (2048/128)
#define HCC 8  // candidate columns per CTA (1024/128)
#define NKS 64 // K=1024 -> 64 mma k-steps of 16
#define KG 4   // k-split groups
#define KPG (NKS / KG) // 16 k-steps per warp
#define PD 4   // A-fragment software-pipeline depth

#define WZR_U4 (NKS * 2 * 32) // 4096 uint4 (64KB)
#define WH_U4  (NKS * 32)     // 2048 uint4 (32KB)
#define RED_F  ((KG - 1) * 4 * 32 * 8) // 3072 floats (12KB)
#define SMEM_SCAN ((WZR_U4 + WH_U4) * 16 + RED_F * 4)

__device__ __forceinline__ void grid_barrier_init()
{
    __threadfence();
    __syncthreads();
    if (threadIdx.x == 0) {
        volatile unsigned* genp = &g_barGen;
        unsigned gen = *genp;
        unsigned arrived = atomicAdd(&g_barCount, 1u);
        if (arrived == NCTA - 1) {
            atomicExch(&g_barCount, 0u);
            __threadfence();
            atomicAdd(&g_barGen, 1u);
        } else {
            while (*genp == gen) { __nanosleep(64); }
        }
    }
    __syncthreads();
    __threadfence();
}

__device__ __forceinline__ void flag_barrier(int c, unsigned target)
{
    __threadfence();
    __syncthreads();
    if (threadIdx.x == 0)
        *(volatile unsigned*)&g_flag[c * 8] = target;
    if (threadIdx.x < NCTA) {
        volatile unsigned* fp = &g_flag[threadIdx.x * 8];
        while (*fp < target) { __nanosleep(32); }
    }
    __syncthreads();
    __threadfence();
}

__global__ __launch_bounds__(STHR, 1) void gru_scan(
    const float* __restrict__ Wz, const float* __restrict__ Wr,
    const float* __restrict__ Wh)
{
    extern __shared__ unsigned char smraw[];
    uint4* wzr4 = (uint4*)smraw;      // [kstep][nt][lane]
    uint4* wh4  = wzr4 + WZR_U4;      // [kstep][lane]
    float* red  = (float*)(wh4 + WH_U4); // [(KG-1)][4 w][32 lane][8]

    const int tid = threadIdx.x;
    const int c = blockIdx.x;
    const int warp = tid >> 5;
    const int lane = tid & 31;
    const int g = warp >> 2;  // k-group 0..3
    const int w = warp & 3;   // row-group 0..3
    const int quad = lane & 3;
    const int mrow = w * 16 + (lane >> 2);
    const int q2 = quad * 2;
    const bool isZ = (c < 64);
    const int ksBeg = g * KPG;

    if (tid == 0) *(volatile unsigned*)&g_flag[c * 8] = 0u;

    // ---- prepack recurrent weight slices into SMEM fragment layout (once) ----
    for (int e = tid; e < NKS * 2 * 32; e += STHR) {
        int kst = e >> 6, nt = (e >> 5) & 1, ln = e & 31;
        int jg = c * ZRC + nt * 8 + (ln >> 2);
        int k0 = kst * 16 + (ln & 3) * 2;
        const float* Wsel;
        int col;
        if (jg < HH) { Wsel = Wz; col = jg; }
        else         { Wsel = Wr; col = jg - HH; }
        float w0 = __ldg(&Wsel[(size_t)(II + k0) * HH + col]);
        float w1 = __ldg(&Wsel[(size_t)(II + k0 + 1) * HH + col]);
        float w8 = __ldg(&Wsel[(size_t)(II + k0 + 8) * HH + col]);
        float w9 = __ldg(&Wsel[(size_t)(II + k0 + 9) * HH + col]);
        unsigned b0h, b0l, b1h, b1l;
        hilo2(w0, w1, b0h, b0l);
        hilo2(w8, w9, b1h, b1l);
        wzr4[e] = make_uint4(b0h, b1h, b0l, b1l);
    }
    for (int e = tid; e < NKS * 32; e += STHR) {
        int kst = e >> 5, ln = e & 31;
        int col = c * HCC + (ln >> 2);
        int k0 = kst * 16 + (ln & 3) * 2;
        float w0 = __ldg(&Wh[(size_t)(II + k0) * HH + col]);
        float w1 = __ldg(&Wh[(size_t)(II + k0 + 1) * HH + col]);
        float w8 = __ldg(&Wh[(size_t)(II + k0 + 8) * HH + col]);
        float w9 = __ldg(&Wh[(size_t)(II + k0 + 9) * HH + col]);
        unsigned b0h, b0l, b1h, b1l;
        hilo2(w0, w1, b0h, b0l);
        hilo2(w8, w9, b1h, b1l);
        wh4[e] = make_uint4(b0h, b1h, b0l, b1l);
    }

    // zero h slot 0 and bf16 h buffer (h0 = 0); redone each launch
    for (int idx = c * STHR + tid; idx < BB * HH; idx += NCTA * STHR) g_h[idx] = 0.f;
    for (int idx = c * STHR + tid; idx < 512 * BB; idx += NCTA * STHR) g_hb[idx] = make_uint2(0u, 0u);
    grid_barrier_init();

    const uint2* hbB  = g_hb  + (size_t)quad * BB + mrow;
    const uint2* hrbB = g_hrb + (size_t)quad * BB + mrow;

#define LOADA(src, ks, j)                                        \
    do {                                                         \
        const uint2* _p = (src) + (size_t)(ks) * (8 * BB);       \
        A0[j] = __ldcg(_p);                                      \
        A1[j] = __ldcg(_p + 8);                                  \
        A2[j] = __ldcg(_p + 4 * BB);                             \
        A3[j] = __ldcg(_p + 4 * BB + 8);                         \
    } while (0)

    unsigned bt = 0;

    for (int t = 0; t < TT; ++t) {
        const float* hprev = g_h + (size_t)t * BB * HH;
        const float* gx = g_gx + (size_t)t * BB * H3;

        // ---------- phase-1 epilogue operand prefetch (g==0 warps only) ----------
        float2 p1gx[2][2], p1hp[2][2];
        if (g == 0) {
#pragma unroll
            for (int nt = 0; nt < 2; ++nt) {
                int jg = c * ZRC + nt * 8 + q2;
                p1gx[nt][0] = ldcg2(&gx[(size_t)mrow * H3 + jg]);
                p1gx[nt][1] = ldcg2(&gx[(size_t)(mrow + 8) * H3 + jg]);
                if (!isZ) {
                    int jr = jg - HH;
                    p1hp[nt][0] = ldcg2(&hprev[(size_t)mrow * HH + jr]);
                    p1hp[nt][1] = ldcg2(&hprev[(size_t)(mrow + 8) * HH + jr]);
                }
            }
        }

        // ================= phase 1: zr = hprev @ Wzr_slice ==================
        float acc1[6][4];
#pragma unroll
        for (int gg = 0; gg < 6; gg++)
#pragma unroll
            for (int i = 0; i < 4; i++) acc1[gg][i] = 0.f;

        {
            uint2 A0[PD], A1[PD], A2[PD], A3[PD];
#pragma unroll
            for (int j = 0; j < PD; ++j) LOADA(hbB, ksBeg + j, j);
#pragma unroll 1
            for (int l8 = 0; l8 < KPG; l8 += PD) {
#pragma unroll
                for (int j = 0; j < PD; ++j) {
                    int l = l8 + j, ks = ksBeg + l;
                    uint2 u0 = A0[j], u1 = A1[j], u2 = A2[j], u3 = A3[j];
                    if (l + PD < KPG) LOADA(hbB, ks + PD, j);
                    uint4 B0 = wzr4[(ks * 2 + 0) * 32 + lane];
                    uint4 B1 = wzr4[(ks * 2 + 1) * 32 + lane];
                    mma16816(acc1[0], u0.x, u1.x, u2.x, u3.x, B0.x, B0.y);
                    mma16816(acc1[1], u0.x, u1.x, u2.x, u3.x, B0.z, B0.w);
                    mma16816(acc1[2], u0.y, u1.y, u2.y, u3.y, B0.x, B0.y);
                    mma16816(acc1[3], u0.x, u1.x, u2.x, u3.x, B1.x, B1.y);
                    mma16816(acc1[4], u0.x, u1.x, u2.x, u3.x, B1.z, B1.w);
                    mma16816(acc1[5], u0.y, u1.y, u2.y, u3.y, B1.x, B1.y);
                }
            }
        }
        // combine 3 products per nt -> 8 partial floats; reduce across k-groups
        float ps[8];
#pragma unroll
        for (int nt = 0; nt < 2; ++nt)
#pragma unroll
            for (int i = 0; i < 4; i++)
                ps[nt * 4 + i] = acc1[nt * 3][i] + acc1[nt * 3 + 1][i] + acc1[nt * 3 + 2][i];
        if (g > 0) {
            float* rp = red + (((g - 1) * 4 + w) * 32 + lane) * 8;
#pragma unroll
            for (int i = 0; i < 8; i++) rp[i] = ps[i];
        }
        __syncthreads();
        if (g == 0) {
#pragma unroll
            for (int gg = 0; gg < KG - 1; ++gg) {
                const float* rp = red + ((gg * 4 + w) * 32 + lane) * 8;
#pragma unroll
                for (int i = 0; i < 8; i++) ps[i] += rp[i];
            }
            // epilogue: add gx, sigmoid, publish z or (h*r) in bf16 hi/lo
#pragma unroll
            for (int nt = 0; nt < 2; ++nt) {
                int jg = c * ZRC + nt * 8 + q2;
                float s0 = ps[nt * 4 + 0], s1 = ps[nt * 4 + 1];
                float s2 = ps[nt * 4 + 2], s3 = ps[nt * 4 + 3];
                if (isZ) {
                    float2 zt = make_float2(sigmoidf_(s0 + p1gx[nt][0].x), sigmoidf_(s1 + p1gx[nt][0].y));
                    float2 zb = make_float2(sigmoidf_(s2 + p1gx[nt][1].x), sigmoidf_(s3 + p1gx[nt][1].y));
                    *(float2*)&g_z[mrow * HH + jg] = zt;
                    *(float2*)&g_z[(mrow + 8) * HH + jg] = zb;
                } else {
                    int kp = (jg - HH) >> 1;
                    float r0 = sigmoidf_(s0 + p1gx[nt][0].x), r1 = sigmoidf_(s1 + p1gx[nt][0].y);
                    float r2 = sigmoidf_(s2 + p1gx[nt][1].x), r3 = sigmoidf_(s3 + p1gx[nt][1].y);
                    unsigned hh, ll;
                    hilo2(r0 * p1hp[nt][0].x, r1 * p1hp[nt][0].y, hh, ll);
                    g_hrb[kp * BB + mrow] = make_uint2(hh, ll);
                    hilo2(r2 * p1hp[nt][1].x, r3 * p1hp[nt][1].y, hh, ll);
                    g_hrb[kp * BB + mrow + 8] = make_uint2(hh, ll);
                }
            }
        }
        flag_barrier(c, ++bt);

        // ---------- phase-2 epilogue operand prefetch (g==0 warps only) ----------
        int j = c * HCC + q2;
        float2 p2gx0, p2gx1, p2z0, p2z1, p2hp0, p2hp1;
        if (g == 0) {
            p2gx0 = ldcg2(&gx[(size_t)mrow * H3 + 2 * HH + j]);
            p2gx1 = ldcg2(&gx[(size_t)(mrow + 8) * H3 + 2 * HH + j]);
            p2z0 = ldcg2(&g_z[mrow * HH + j]);
            p2z1 = ldcg2(&g_z[(mrow + 8) * HH + j]);
            p2hp0 = ldcg2(&hprev[(size_t)mrow * HH + j]);
            p2hp1 = ldcg2(&hprev[(size_t)(mrow + 8) * HH + j]);
        }

        // ================= phase 2: cand = (h*r) @ Wh_slice =================
        float acc2[6][4];
#pragma unroll
        for (int gg = 0; gg < 6; gg++)
#pragma unroll
            for (int i = 0; i < 4; i++) acc2[gg][i] = 0.f;

        {
            uint2 A0[PD], A1[PD], A2[PD], A3[PD];
#pragma unroll
            for (int jj = 0; jj < PD; ++jj) LOADA(hrbB, ksBeg + jj, jj);
#pragma unroll 1
            for (int l8 = 0; l8 < KPG; l8 += PD) {
#pragma unroll
                for (int jj = 0; jj < PD; ++jj) {
                    int l = l8 + jj, ks = ksBeg + l;
                    uint2 u0 = A0[jj], u1 = A1[jj], u2 = A2[jj], u3 = A3[jj];
                    if (l + PD < KPG) LOADA(hrbB, ks + PD, jj);
                    uint4 Bw = wh4[ks * 32 + lane];
                    int g0 = (ks & 1) * 3;
                    mma16816(acc2[g0 + 0], u0.x, u1.x, u2.x, u3.x, Bw.x, Bw.y);
                    mma16816(acc2[g0 + 1], u0.x, u1.x, u2.x, u3.x, Bw.z, Bw.w);
                    mma16816(acc2[g0 + 2], u0.y, u1.y, u2.y, u3.y, Bw.x, Bw.y);
                }
            }
        }
        float qs[4];
        qs[0] = qs[1] = qs[2] = qs[3] = 0.f;
#pragma unroll
        for (int gg = 0; gg < 6; gg++)
#pragma unroll
            for (int i = 0; i < 4; i++) qs[i] += acc2[gg][i];
        if (g > 0) {
            float* rp = red + (((g - 1) * 4 + w) * 32 + lane) * 8;
#pragma unroll
            for (int i = 0; i < 4; i++) rp[i] = qs[i];
        }
        __syncthreads();
        if (g == 0) {
#pragma unroll
            for (int gg = 0; gg < KG - 1; ++gg) {
                const float* rp = red + ((gg * 4 + w) * 32 + lane) * 8;
#pragma unroll
                for (int i = 0; i < 4; i++) qs[i] += rp[i];
            }
            // epilogue: h_new = z*h + (1-z)*sigmoid(cand)
            float c0 = sigmoidf_(qs[0] + p2gx0.x), c1 = sigmoidf_(qs[1] + p2gx0.y);
            float c2 = sigmoidf_(qs[2] + p2gx1.x), c3 = sigmoidf_(qs[3] + p2gx1.y);
            float hn0 = p2z0.x * p2hp0.x + (1.f - p2z0.x) * c0;
            float hn1 = p2z0.y * p2hp0.y + (1.f - p2z0.y) * c1;
            float hn2 = p2z1.x * p2hp1.x + (1.f - p2z1.x) * c2;
            float hn3 = p2z1.y * p2hp1.y + (1.f - p2z1.y) * c3;
            float* hnew = g_h + (size_t)(t + 1) * BB * HH;
            *(float2*)&hnew[(size_t)mrow * HH + j] = make_float2(hn0, hn1);
            *(float2*)&hnew[(size_t)(mrow + 8) * HH + j] = make_float2(hn2, hn3);
            int kp = j >> 1;
            unsigned hh, ll;
            hilo2(hn0, hn1, hh, ll);
            g_hb[kp * BB + mrow] = make_uint2(hh, ll);
            hilo2(hn2, hn3, hh, ll);
            g_hb[kp * BB + mrow + 8] = make_uint2(hh, ll);
        }
        flag_barrier(c, ++bt);
    }
#undef LOADA
}

// ---------------------------------------------------------------------------
extern "C" void kernel_launch(void* const* d_in, const int* in_sizes, int n_in,
                              void* d_out, int out_size)
{
    const float* x  = (const float*)d_in[0];
    const float* Wz = (const float*)d_in[1];
    const float* bz = (const float*)d_in[2];
    const float* Wr = (const float*)d_in[3];
    const float* br = (const float*)d_in[4];
    const float* Wh = (const float*)d_in[5];
    const float* bh = (const float*)d_in[6];
    const float* Wo = (const float*)d_in[7];
    const float* bo = (const float*)d_in[8];
    float* out = (float*)d_out;
    (void)in_sizes; (void)n_in; (void)out_size;

    float *gx = nullptr, *hall = nullptr;
    uint4 *wfz = nullptr, *wfr = nullptr, *wfh = nullptr, *wfo = nullptr;
    cudaGetSymbolAddress((void**)&gx, g_gx);
    cudaGetSymbolAddress((void**)&hall, g_h);
    cudaGetSymbolAddress((void**)&wfz, g_wfz);
    cudaGetSymbolAddress((void**)&wfr, g_wfr);
    cudaGetSymbolAddress((void**)&wfh, g_wfh);
    cudaGetSymbolAddress((void**)&wfo, g_wfo);

    cudaFuncSetAttribute(gru_scan, cudaFuncAttributeMaxDynamicSharedMemorySize, SMEM_SCAN);

    // 0) pack fragments
    int preTot = (II / 16) * (HH / 8) * 32;
    int postTot = (HH / 16) * (OO / 8) * 32;
    pack_wfrag<<<(preTot + 255) / 256, 256>>>(Wz, wfz, II, HH);
    pack_wfrag<<<(preTot + 255) / 256, 256>>>(Wr, wfr, II, HH);
    pack_wfrag<<<(preTot + 255) / 256, 256>>>(Wh, wfh, II, HH);
    pack_wfrag<<<(postTot + 255) / 256, 256>>>(Wo, wfo, HH, OO);

    // 1) pre-GEMMs
    dim3 gpre(HH / 64, TB / 128);
    mma_gemm_bias<<<gpre, 256>>>(x, wfz, bz, gx + 0,      II, II, HH / 8, H3);
    mma_gemm_bias<<<gpre, 256>>>(x, wfr, br, gx + HH,     II, II, HH / 8, H3);
    mma_gemm_bias<<<gpre, 256>>>(x, wfh, bh, gx + 2 * HH, II, II, HH / 8, H3);

    // 2) persistent recurrent scan
    gru_scan<<<NCTA, STHR, SMEM_SCAN>>>(Wz, Wr, Wh);

    // 3) post-GEMM
    dim3 gpost(OO / 64, TB / 128);
    mma_gemm_bias<<<gpost, 256>>>(hall + BB * HH, wfo, bo, out, HH, HH, OO / 8, OO);
}